// round 12
// baseline (speedup 1.0000x reference)
#include <cuda_runtime.h>

// out[b, 0, h, w] = 0.5f * (x[b,0,h,w] + x[b,1,h,w] + x[b,2,h,w])
// Exact algebraic collapse of the diagonal Haar decompose + reconstruct:
//   recon(0::2,1::2) = 0.5*(up_low+up_det) = 0.5*sum_c x01
//   recon(1::2,0::2) = 0.5*(up_low-up_det) = 0.5*sum_c x10
//   recon(0::2,0::2) = 0.5*(dn_low+dn_det) = 0.5*sum_c x00
//   recon(1::2,1::2) = 0.5*(dn_low-dn_det) = 0.5*sum_c x11
// i.e. every output pixel = 0.5 * channel-sum at the same spatial location.
//
// R12: R1 shape (4M threads, one float4 per thread, MLP=3 — session-best
// DRAM%=84.5 sample) + streaming stores. Population axis: the only two
// regressions in 11 rounds came from REDUCING thread count (R4: 1M, R8:
// 303K); 4M is the one untested point above the proven-good 2M. All warp
// accesses remain contiguous 512B. Expected within noise of the 36.2-37.5us
// HBM floor (268.4 MB @ 7.2-7.4 TB/s, 90-93% of spec).

static constexpr int B = 16;
static constexpr int C = 3;
static constexpr long long HW = 1024LL * 1024LL;            // elems per plane (2^20)
static constexpr long long OUT_ELEMS = (long long)B * HW;   // 16,777,216
static constexpr long long OUT_VECS = OUT_ELEMS / 4;        // 4,194,304 float4s
static constexpr int THREADS = 256;
static constexpr int GRID = (int)(OUT_VECS / THREADS);      // 16384, exact cover

__global__ void __launch_bounds__(THREADS) haar_chansum_kernel(
    const float* __restrict__ x, float* __restrict__ out) {
    long long v = (long long)blockIdx.x * THREADS + threadIdx.x;
    long long e = v * 4;                   // element index (float4-aligned)
    long long b = e >> 20;                 // batch (HW = 2^20)
    long long p = e & (HW - 1);            // pixel within plane
    const float* base = x + (b * C) * HW + p;

    // 3 independent, fully-coalesced LDG.128 (each warp access = 512B contiguous)
    float4 a0 = *reinterpret_cast<const float4*>(base);
    float4 a1 = *reinterpret_cast<const float4*>(base + HW);
    float4 a2 = *reinterpret_cast<const float4*>(base + 2LL * HW);

    float4 r;
    r.x = 0.5f * (a0.x + a1.x + a2.x);
    r.y = 0.5f * (a0.y + a1.y + a2.y);
    r.z = 0.5f * (a0.z + a1.z + a2.z);
    r.w = 0.5f * (a0.w + a1.w + a2.w);

    __stcs(reinterpret_cast<float4*>(out + e), r);
}

extern "C" void kernel_launch(void* const* d_in, const int* in_sizes, int n_in,
                              void* d_out, int out_size) {
    const float* x = (const float*)d_in[0];
    float* out = (float*)d_out;
    haar_chansum_kernel<<<GRID, THREADS>>>(x, out);
}